// round 1
// baseline (speedup 1.0000x reference)
#include <cuda_runtime.h>
#include <cuda_bf16.h>

// Problem constants
#define BB 8
#define MM 512
#define HH 512
#define KK 8
#define DD 64
#define LL 1024
#define NN 1536   // M + L

// Scratch (device globals: allocation-free rule)
__device__ float g_q[64 * MM * DD];     // [bh, m, d]      8 MB
__device__ float g_k[64 * NN * DD];     // [bh, n, d]     24 MB
__device__ float g_v[64 * NN * DD];     // [bh, n, d]     24 MB
__device__ float g_ao[BB * MM * HH];    // [b*m, h]        8 MB

// ---------------------------------------------------------------------------
// GEMM: C[r, j] = sum_{h<512} A[r, h] * W[j, h]   (A: [R,512], W: [512,512])
// MODE 0: plain row-major write C[r*512 + j]
// MODE 1: head scatter: b = r/T, t = r%T, head = j>>6, d = j&63
//         C[((b*8+head)*T + t)*64 + d]
// Tile 64x64, k-chunk 16, 256 threads, 4x4 per thread.
// ---------------------------------------------------------------------------
template <int MODE>
__global__ void __launch_bounds__(256) gemm512(const float* __restrict__ A,
                                               const float* __restrict__ W,
                                               float* __restrict__ C, int T) {
    __shared__ float As[16][64];
    __shared__ float Ws[16][64];
    const int tx = threadIdx.x & 15;
    const int ty = threadIdx.x >> 4;
    const int rb = blockIdx.x * 64;
    const int jb = blockIdx.y * 64;

    float acc[4][4] = {};

    for (int hh = 0; hh < 512; hh += 16) {
#pragma unroll
        for (int e = 0; e < 4; e++) {
            int lin = threadIdx.x + e * 256;
            int rr = lin >> 4, hc = lin & 15;
            As[hc][rr] = A[(size_t)(rb + rr) * 512 + hh + hc];
            Ws[hc][rr] = W[(size_t)(jb + rr) * 512 + hh + hc];
        }
        __syncthreads();
#pragma unroll
        for (int kk = 0; kk < 16; kk++) {
            float4 a4 = reinterpret_cast<const float4*>(As[kk])[ty];
            float4 w4 = reinterpret_cast<const float4*>(Ws[kk])[tx];
            float a[4] = {a4.x, a4.y, a4.z, a4.w};
            float w[4] = {w4.x, w4.y, w4.z, w4.w};
#pragma unroll
            for (int i = 0; i < 4; i++)
#pragma unroll
                for (int j = 0; j < 4; j++) acc[i][j] += a[i] * w[j];
        }
        __syncthreads();
    }

#pragma unroll
    for (int i = 0; i < 4; i++) {
        int r = rb + ty * 4 + i;
#pragma unroll
        for (int j = 0; j < 4; j++) {
            int jj = jb + tx * 4 + j;
            if (MODE == 0) {
                C[(size_t)r * 512 + jj] = acc[i][j];
            } else {
                int b = r / T, t = r % T;
                int head = jj >> 6, d = jj & 63;
                C[(((size_t)(b * 8 + head) * T + t) << 6) + d] = acc[i][j];
            }
        }
    }
}

// ---------------------------------------------------------------------------
// Banded attention: block = (m, bh), 128 threads.
// score(l) = q[m] . (k[m+l] + pe[:, l]) * 0.125 for l in [0, 1024)
// softmax over l, then o[d] = sum_l p[l] * v[m+l, d]
// Writes ao[(b*512 + m)*512 + h*64 + d]  (b = bh>>3, h = bh&7)
// ---------------------------------------------------------------------------
__global__ void __launch_bounds__(128) attn_kernel(const float* __restrict__ q,
                                                   const float* __restrict__ k,
                                                   const float* __restrict__ v,
                                                   const float* __restrict__ pe,
                                                   float* __restrict__ ao) {
    const int m = blockIdx.x;
    const int bh = blockIdx.y;
    const int t = threadIdx.x;  // 0..127

    __shared__ float qs[64];
    __shared__ float sc[1024];
    __shared__ float red[128];

    const float* qp = q + ((size_t)bh * MM + m) * DD;
    if (t < 64) qs[t] = qp[t];
    __syncthreads();

    const float* kb = k + ((size_t)bh * NN + m) * DD;  // row l -> kb + l*64

    // Phase 1: scores (each thread does 8 window positions)
    float smax = -1e30f;
#pragma unroll
    for (int i = 0; i < 8; i++) {
        int l = t + i * 128;
        const float4* kr = reinterpret_cast<const float4*>(kb + (size_t)l * 64);
        float dot = 0.f;
#pragma unroll
        for (int dv = 0; dv < 16; dv++) {
            float4 kv = kr[dv];
            int d = dv * 4;
            dot += qs[d + 0] * (kv.x + pe[(d + 0) * LL + l]);
            dot += qs[d + 1] * (kv.y + pe[(d + 1) * LL + l]);
            dot += qs[d + 2] * (kv.z + pe[(d + 2) * LL + l]);
            dot += qs[d + 3] * (kv.w + pe[(d + 3) * LL + l]);
        }
        dot *= 0.125f;  // 1/sqrt(64)
        sc[l] = dot;
        smax = fmaxf(smax, dot);
    }

    // Block max
    red[t] = smax;
    __syncthreads();
    for (int s = 64; s > 0; s >>= 1) {
        if (t < s) red[t] = fmaxf(red[t], red[t + s]);
        __syncthreads();
    }
    float gmax = red[0];
    __syncthreads();

    // Exponentials + block sum
    float psum = 0.f;
#pragma unroll
    for (int i = 0; i < 8; i++) {
        int l = t + i * 128;
        float p = __expf(sc[l] - gmax);
        sc[l] = p;
        psum += p;
    }
    red[t] = psum;
    __syncthreads();
    for (int s = 64; s > 0; s >>= 1) {
        if (t < s) red[t] += red[t + s];
        __syncthreads();
    }
    float inv = 1.f / red[0];
    __syncthreads();  // protect red before reuse

    // Phase 3: o[d] = sum_l p[l] * v[m+l, d]; two threads per d (halves of l)
    const int d = t & 63;
    const int half = t >> 6;
    const float* vb = v + ((size_t)bh * NN + m) * DD + d;
    float o = 0.f;
    int l0 = half * 512;
#pragma unroll 8
    for (int l = l0; l < l0 + 512; l++) o += sc[l] * vb[(size_t)l * 64];
    red[t] = o;
    __syncthreads();
    if (t < 64) {
        float val = (red[t] + red[t + 64]) * inv;
        int b = bh >> 3, h = bh & 7;
        ao[((size_t)(b * MM + m) * HH) + h * 64 + t] = val;
    }
}

// ---------------------------------------------------------------------------
extern "C" void kernel_launch(void* const* d_in, const int* in_sizes, int n_in,
                              void* d_out, int out_size) {
    const float* query  = (const float*)d_in[0];  // [8, 512, 512]
    const float* key    = (const float*)d_in[1];  // [8, 1536, 512]
    const float* value  = (const float*)d_in[2];  // [8, 1536, 512]
    const float* key_pe = (const float*)d_in[3];  // [1, 64, 1024]
    const float* Wq     = (const float*)d_in[4];  // [512, 512]
    const float* Wk     = (const float*)d_in[5];
    const float* Wv     = (const float*)d_in[6];
    const float* Wo     = (const float*)d_in[7];
    float* out = (float*)d_out;                   // [8, 512, 512]

    float *qb, *kb, *vb, *aob;
    cudaGetSymbolAddress((void**)&qb, g_q);
    cudaGetSymbolAddress((void**)&kb, g_k);
    cudaGetSymbolAddress((void**)&vb, g_v);
    cudaGetSymbolAddress((void**)&aob, g_ao);

    dim3 thr(256);
    // Q projection: R = 8*512 = 4096 rows
    gemm512<1><<<dim3(4096 / 64, 8), thr>>>(query, Wq, qb, MM);
    // K/V projections: R = 8*1536 = 12288 rows
    gemm512<1><<<dim3(12288 / 64, 8), thr>>>(key, Wk, kb, NN);
    gemm512<1><<<dim3(12288 / 64, 8), thr>>>(value, Wv, vb, NN);

    // Attention: grid (m, bh)
    attn_kernel<<<dim3(MM, 64), 128>>>(qb, kb, vb, key_pe, aob);

    // Output projection
    gemm512<0><<<dim3(4096 / 64, 8), thr>>>(aob, Wo, out, MM);
}

// round 2
// speedup vs baseline: 2.2461x; 2.2461x over previous
#include <cuda_runtime.h>
#include <cuda_bf16.h>

// Problem constants
#define BB 8
#define MM 512
#define HH 512
#define KK 8
#define DD 64
#define LL 1024
#define NN 1536   // M + L

// Scratch (device globals: allocation-free rule)
__device__ float g_q[64 * MM * DD];     // [bh, m, d]      8 MB
__device__ float g_k[64 * NN * DD];     // [bh, n, d]     24 MB
__device__ float g_v[64 * NN * DD];     // [bh, n, d]     24 MB
__device__ float g_ao[BB * MM * HH];    // [b*m, h]        8 MB

// ---------------------------------------------------------------------------
// GEMM: C[r, j] = sum_{h<512} A[r, h] * W[j, h]
// MODE 0: plain row-major write; MODE 1: head scatter.
// ---------------------------------------------------------------------------
template <int MODE>
__global__ void __launch_bounds__(256) gemm512(const float* __restrict__ A,
                                               const float* __restrict__ W,
                                               float* __restrict__ C, int T) {
    __shared__ float As[16][64];
    __shared__ float Ws[16][64];
    const int tx = threadIdx.x & 15;
    const int ty = threadIdx.x >> 4;
    const int rb = blockIdx.x * 64;
    const int jb = blockIdx.y * 64;

    float acc[4][4] = {};

    for (int hh = 0; hh < 512; hh += 16) {
#pragma unroll
        for (int e = 0; e < 4; e++) {
            int lin = threadIdx.x + e * 256;
            int rr = lin >> 4, hc = lin & 15;
            As[hc][rr] = A[(size_t)(rb + rr) * 512 + hh + hc];
            Ws[hc][rr] = W[(size_t)(jb + rr) * 512 + hh + hc];
        }
        __syncthreads();
#pragma unroll
        for (int kk = 0; kk < 16; kk++) {
            float4 a4 = reinterpret_cast<const float4*>(As[kk])[ty];
            float4 w4 = reinterpret_cast<const float4*>(Ws[kk])[tx];
            float a[4] = {a4.x, a4.y, a4.z, a4.w};
            float w[4] = {w4.x, w4.y, w4.z, w4.w};
#pragma unroll
            for (int i = 0; i < 4; i++)
#pragma unroll
                for (int j = 0; j < 4; j++) acc[i][j] += a[i] * w[j];
        }
        __syncthreads();
    }

#pragma unroll
    for (int i = 0; i < 4; i++) {
        int r = rb + ty * 4 + i;
#pragma unroll
        for (int j = 0; j < 4; j++) {
            int jj = jb + tx * 4 + j;
            if (MODE == 0) {
                C[(size_t)r * 512 + jj] = acc[i][j];
            } else {
                int b = r / T, t = r % T;
                int head = jj >> 6, d = jj & 63;
                C[(((size_t)(b * 8 + head) * T + t) << 6) + d] = acc[i][j];
            }
        }
    }
}

// ---------------------------------------------------------------------------
// Tiled banded attention (flash-style, absolute-n coordinates).
// Block = (m-tile of 64, bh). 256 threads as 16x16.
// S[m][n] = q[m].k[n] + q[m].pe[:, n-m], valid iff 0 <= n-m < 1024.
// 17 key chunks of 64. Online softmax; O in registers.
// ---------------------------------------------------------------------------
#define ATTN_SMEM_FLOATS (64*68*3 + 64*64 + 64*128)

__global__ void __launch_bounds__(256) attn2(const float* __restrict__ q,
                                             const float* __restrict__ k,
                                             const float* __restrict__ v,
                                             const float* __restrict__ pe,
                                             float* __restrict__ ao) {
    extern __shared__ float sm[];
    float* sQt = sm;                    // [d][m] stride 68
    float* sKt = sm + 64 * 68;          // [d][n] stride 68
    float* sPs = sm + 64 * 68 * 2;      // [m][n] stride 68
    float* sVs = sm + 64 * 68 * 3;      // [n][d] stride 64
    float* sPe = sVs + 64 * 64;         // [d][128]

    const int m0 = blockIdx.x * 64;
    const int bh = blockIdx.y;
    const int t = threadIdx.x;
    const int tx = t & 15;
    const int ty = t >> 4;
    const int r = t >> 2;       // 0..63 (row for loads)
    const int seg = t & 3;      // 4 threads per row

    // ---- load Q tile transposed: Qt[d][m] ----
    {
        const float* qg = q + ((size_t)bh * MM + m0) * DD + (size_t)r * DD;
#pragma unroll
        for (int w = 0; w < 4; w++) {
            int d0 = seg * 16 + w * 4;
            float4 val = *(const float4*)(qg + d0);
            sQt[(d0 + 0) * 68 + r] = val.x;
            sQt[(d0 + 1) * 68 + r] = val.y;
            sQt[(d0 + 2) * 68 + r] = val.z;
            sQt[(d0 + 3) * 68 + r] = val.w;
        }
    }

    float o[4][4] = {};
    float rmax[4], rsum[4];
#pragma unroll
    for (int i = 0; i < 4; i++) { rmax[i] = -3.0e38f; rsum[i] = 0.f; }

    const int pshift = 61 + 4 * (tx - ty);  // 64 - 3 + 4*(tx-ty), in [1,121]

    for (int c = 0; c < 17; c++) {
        __syncthreads();  // previous chunk done with sKt/sVs/sPs (and Qt ready)

        // ---- load K chunk (transposed) and V chunk ----
        {
            const size_t base = ((size_t)bh * NN + m0 + c * 64 + r) * DD;
            const float* kg = k + base;
            const float* vg = v + base;
#pragma unroll
            for (int w = 0; w < 4; w++) {
                int d0 = seg * 16 + w * 4;
                float4 kv4 = *(const float4*)(kg + d0);
                sKt[(d0 + 0) * 68 + r] = kv4.x;
                sKt[(d0 + 1) * 68 + r] = kv4.y;
                sKt[(d0 + 2) * 68 + r] = kv4.z;
                sKt[(d0 + 3) * 68 + r] = kv4.w;
                float4 vv4 = *(const float4*)(vg + d0);
                *(float4*)&sVs[r * 64 + d0] = vv4;
            }
        }
        // ---- load pe slice: cols [64*(c-1), 64*(c-1)+127], OOB -> 0 ----
        {
            int lbase = (c - 1) * 64;
#pragma unroll
            for (int it = 0; it < 8; it++) {
                int idx = t + it * 256;        // float4 index, 2048 total
                int d = idx >> 5;
                int col = (idx & 31) << 2;
                int gl = lbase + col;
                float4 pv;
                if (gl >= 0 && gl < LL) pv = *(const float4*)(pe + (size_t)d * LL + gl);
                else pv = make_float4(0.f, 0.f, 0.f, 0.f);
                *(float4*)&sPe[d * 128 + col] = pv;
            }
        }
        __syncthreads();

        // ---- scores ----
        float acc[4][4] = {};
#pragma unroll 2
        for (int d = 0; d < 64; d++) {
            const float4 qv = *(const float4*)&sQt[d * 68 + (ty << 2)];
            const float4 kv = *(const float4*)&sKt[d * 68 + (tx << 2)];
            const float* pb = &sPe[d * 128 + pshift];
            float pe7[7];
#pragma unroll
            for (int s = 0; s < 7; s++) pe7[s] = pb[s];
            const float qa[4] = {qv.x, qv.y, qv.z, qv.w};
            const float ka[4] = {kv.x, kv.y, kv.z, kv.w};
#pragma unroll
            for (int i = 0; i < 4; i++)
#pragma unroll
                for (int j = 0; j < 4; j++) {
                    acc[i][j] += qa[i] * ka[j];
                    acc[i][j] += qa[i] * pe7[3 + j - i];
                }
        }
#pragma unroll
        for (int i = 0; i < 4; i++)
#pragma unroll
            for (int j = 0; j < 4; j++) acc[i][j] *= 0.125f;

        // ---- band mask (only boundary chunks can violate) ----
        if (c == 0 || c == 16) {
#pragma unroll
            for (int i = 0; i < 4; i++)
#pragma unroll
                for (int j = 0; j < 4; j++) {
                    int lrel = 64 * c + (tx * 4 + j) - (ty * 4 + i);
                    if (lrel < 0 || lrel >= LL) acc[i][j] = -1.0e30f;
                }
        }

        // ---- online softmax ----
        float p[4][4];
#pragma unroll
        for (int i = 0; i < 4; i++) {
            float mx = fmaxf(fmaxf(acc[i][0], acc[i][1]), fmaxf(acc[i][2], acc[i][3]));
#pragma unroll
            for (int off = 8; off > 0; off >>= 1)
                mx = fmaxf(mx, __shfl_xor_sync(0xffffffffu, mx, off, 16));
            float nm = fmaxf(rmax[i], mx);
            float corr = __expf(rmax[i] - nm);
            float ls = 0.f;
#pragma unroll
            for (int j = 0; j < 4; j++) {
                p[i][j] = __expf(acc[i][j] - nm);
                ls += p[i][j];
            }
#pragma unroll
            for (int off = 8; off > 0; off >>= 1)
                ls += __shfl_xor_sync(0xffffffffu, ls, off, 16);
            rsum[i] = rsum[i] * corr + ls;
            rmax[i] = nm;
#pragma unroll
            for (int j = 0; j < 4; j++) o[i][j] *= corr;
        }

        // ---- write P ----
#pragma unroll
        for (int i = 0; i < 4; i++) {
            float4 pv = make_float4(p[i][0], p[i][1], p[i][2], p[i][3]);
            *(float4*)&sPs[(ty * 4 + i) * 68 + tx * 4] = pv;
        }
        __syncthreads();

        // ---- P . V ----
#pragma unroll 4
        for (int nl = 0; nl < 64; nl++) {
            float4 vv = *(const float4*)&sVs[nl * 64 + (tx << 2)];
            float pa[4];
#pragma unroll
            for (int i = 0; i < 4; i++) pa[i] = sPs[(ty * 4 + i) * 68 + nl];
            const float va[4] = {vv.x, vv.y, vv.z, vv.w};
#pragma unroll
            for (int i = 0; i < 4; i++)
#pragma unroll
                for (int j = 0; j < 4; j++) o[i][j] += pa[i] * va[j];
        }
    }

    // ---- epilogue: normalize + write ao[(b*512+m)*512 + h*64 + d] ----
    const int b = bh >> 3, h = bh & 7;
#pragma unroll
    for (int i = 0; i < 4; i++) {
        float inv = 1.f / rsum[i];
        int m = m0 + ty * 4 + i;
        float4 ov = make_float4(o[i][0] * inv, o[i][1] * inv, o[i][2] * inv, o[i][3] * inv);
        *(float4*)&ao[((size_t)(b * MM + m) * HH) + h * 64 + tx * 4] = ov;
    }
}

// ---------------------------------------------------------------------------
extern "C" void kernel_launch(void* const* d_in, const int* in_sizes, int n_in,
                              void* d_out, int out_size) {
    const float* query  = (const float*)d_in[0];
    const float* key    = (const float*)d_in[1];
    const float* value  = (const float*)d_in[2];
    const float* key_pe = (const float*)d_in[3];
    const float* Wq     = (const float*)d_in[4];
    const float* Wk     = (const float*)d_in[5];
    const float* Wv     = (const float*)d_in[6];
    const float* Wo     = (const float*)d_in[7];
    float* out = (float*)d_out;

    float *qb, *kb, *vb, *aob;
    cudaGetSymbolAddress((void**)&qb, g_q);
    cudaGetSymbolAddress((void**)&kb, g_k);
    cudaGetSymbolAddress((void**)&vb, g_v);
    cudaGetSymbolAddress((void**)&aob, g_ao);

    static bool attr_set = false;
    if (!attr_set) {
        cudaFuncSetAttribute(attn2, cudaFuncAttributeMaxDynamicSharedMemorySize,
                             ATTN_SMEM_FLOATS * sizeof(float));
        attr_set = true;
    }

    dim3 thr(256);
    gemm512<1><<<dim3(4096 / 64, 8), thr>>>(query, Wq, qb, MM);
    gemm512<1><<<dim3(12288 / 64, 8), thr>>>(key, Wk, kb, NN);
    gemm512<1><<<dim3(12288 / 64, 8), thr>>>(value, Wv, vb, NN);

    attn2<<<dim3(MM / 64, 64), thr, ATTN_SMEM_FLOATS * sizeof(float)>>>(
        qb, kb, vb, key_pe, aob);

    gemm512<0><<<dim3(4096 / 64, 8), thr>>>(aob, Wo, out, MM);
}

// round 4
// speedup vs baseline: 4.3874x; 1.9534x over previous
#include <cuda_runtime.h>
#include <cuda_bf16.h>
#include <cstdint>

// Problem constants
#define BB 8
#define MM 512
#define HH 512
#define DD 64
#define LL 1024
#define NN 1536   // M + L

// ---------------------------------------------------------------------------
// Scratch (device globals: allocation-free rule)
// ---------------------------------------------------------------------------
__device__ float g_q[64 * MM * DD];     // [bh, m, d] fp32
__device__ float g_k[64 * NN * DD];     // [bh, n, d] fp32
__device__ float g_v[64 * NN * DD];     // [bh, n, d] fp32
__device__ float g_ao[BB * MM * HH];    // [b*m, h]   fp32

__device__ __nv_bfloat16 g_qh[BB * MM * HH], g_ql[BB * MM * HH];
__device__ __nv_bfloat16 g_kh[BB * NN * HH], g_kl[BB * NN * HH];
__device__ __nv_bfloat16 g_vh[BB * NN * HH], g_vl[BB * NN * HH];
__device__ __nv_bfloat16 g_aoh[BB * MM * HH], g_aol[BB * MM * HH];
__device__ __nv_bfloat16 g_wh[4 * HH * HH], g_wl[4 * HH * HH];  // Wq,Wk,Wv,Wo

// ---------------------------------------------------------------------------
// PTX helpers (sm_80-era instructions only; valid for compute_103 PTX target)
// ---------------------------------------------------------------------------
__device__ __forceinline__ uint32_t smem_u32(const void* p) {
    uint32_t a;
    asm("{ .reg .u64 t; cvta.to.shared.u64 t, %1; cvt.u32.u64 %0, t; }"
        : "=r"(a) : "l"(p));
    return a;
}
#define CP_ASYNC16(dst, src) \
    asm volatile("cp.async.cg.shared.global [%0], [%1], 16;" \
                 :: "r"(dst), "l"(src) : "memory")
#define CP_COMMIT() asm volatile("cp.async.commit_group;" ::: "memory")
#define CP_WAIT1() asm volatile("cp.async.wait_group 1;" ::: "memory")
#define CP_WAIT0() asm volatile("cp.async.wait_group 0;" ::: "memory")

__device__ __forceinline__ void ldsm4(uint32_t* r, uint32_t a) {
    asm volatile("ldmatrix.sync.aligned.m8n8.x4.shared.b16 {%0,%1,%2,%3}, [%4];"
                 : "=r"(r[0]), "=r"(r[1]), "=r"(r[2]), "=r"(r[3]) : "r"(a));
}
__device__ __forceinline__ void mma16816(float* c, const uint32_t* a,
                                         const uint32_t* b) {
    asm volatile(
        "mma.sync.aligned.m16n8k16.row.col.f32.bf16.bf16.f32 "
        "{%0,%1,%2,%3}, {%4,%5,%6,%7}, {%8,%9}, {%0,%1,%2,%3};"
        : "+f"(c[0]), "+f"(c[1]), "+f"(c[2]), "+f"(c[3])
        : "r"(a[0]), "r"(a[1]), "r"(a[2]), "r"(a[3]), "r"(b[0]), "r"(b[1]));
}

// ---------------------------------------------------------------------------
// Split fp32 -> bf16 hi/lo  (hi = bf16(x), lo = bf16(x - hi))
// ---------------------------------------------------------------------------
__global__ void __launch_bounds__(256) split_bf16(const float* __restrict__ x,
                                                  __nv_bfloat16* __restrict__ hi,
                                                  __nv_bfloat16* __restrict__ lo,
                                                  int n4) {
    int i = blockIdx.x * 256 + threadIdx.x;
    if (i >= n4) return;
    float4 v = ((const float4*)x)[i];
    __nv_bfloat16 h0 = __float2bfloat16(v.x), h1 = __float2bfloat16(v.y);
    __nv_bfloat16 h2 = __float2bfloat16(v.z), h3 = __float2bfloat16(v.w);
    __nv_bfloat16 l0 = __float2bfloat16(v.x - __bfloat162float(h0));
    __nv_bfloat16 l1 = __float2bfloat16(v.y - __bfloat162float(h1));
    __nv_bfloat16 l2 = __float2bfloat16(v.z - __bfloat162float(h2));
    __nv_bfloat16 l3 = __float2bfloat16(v.w - __bfloat162float(h3));
    ((__nv_bfloat162*)hi)[2 * i]     = __nv_bfloat162(h0, h1);
    ((__nv_bfloat162*)hi)[2 * i + 1] = __nv_bfloat162(h2, h3);
    ((__nv_bfloat162*)lo)[2 * i]     = __nv_bfloat162(l0, l1);
    ((__nv_bfloat162*)lo)[2 * i + 1] = __nv_bfloat162(l2, l3);
}

__global__ void __launch_bounds__(256) split_w4(const float* __restrict__ w0,
                                                const float* __restrict__ w1,
                                                const float* __restrict__ w2,
                                                const float* __restrict__ w3,
                                                __nv_bfloat16* __restrict__ hi,
                                                __nv_bfloat16* __restrict__ lo) {
    const float* src = (blockIdx.y == 0) ? w0 : (blockIdx.y == 1) ? w1
                     : (blockIdx.y == 2) ? w2 : w3;
    int i = blockIdx.x * 256 + threadIdx.x;
    size_t base2 = (size_t)blockIdx.y * (HH * HH / 2);
    float4 v = ((const float4*)src)[i];
    __nv_bfloat16 h0 = __float2bfloat16(v.x), h1 = __float2bfloat16(v.y);
    __nv_bfloat16 h2 = __float2bfloat16(v.z), h3 = __float2bfloat16(v.w);
    __nv_bfloat16 l0 = __float2bfloat16(v.x - __bfloat162float(h0));
    __nv_bfloat16 l1 = __float2bfloat16(v.y - __bfloat162float(h1));
    __nv_bfloat16 l2 = __float2bfloat16(v.z - __bfloat162float(h2));
    __nv_bfloat16 l3 = __float2bfloat16(v.w - __bfloat162float(h3));
    ((__nv_bfloat162*)hi)[base2 + 2 * i]     = __nv_bfloat162(h0, h1);
    ((__nv_bfloat162*)hi)[base2 + 2 * i + 1] = __nv_bfloat162(h2, h3);
    ((__nv_bfloat162*)lo)[base2 + 2 * i]     = __nv_bfloat162(l0, l1);
    ((__nv_bfloat162*)lo)[base2 + 2 * i + 1] = __nv_bfloat162(l2, l3);
}

// ---------------------------------------------------------------------------
// HMMA GEMM: C[r,j] = sum_h A[r,h]*W[j,h] via 3-term bf16 split.
// CTA 128x128; 8 warps (4m x 2n), warp tile 32x64 (m16n8k16 frags).
// 48 chunks of k=32: term0 Ah*Wh, term1 Ah*Wl, term2 Al*Wh.
// cp.async 2-stage pipeline; smem rows padded to 80B (conflict-free ldmatrix).
// MODE 0: row-major write; MODE 1: head scatter.
// ---------------------------------------------------------------------------
#define STAGE_BYTES 20480           // A 128*80 + W 128*80

template <int MODE>
__global__ void __launch_bounds__(256) gemm_mma(const __nv_bfloat16* __restrict__ Ah,
                                                const __nv_bfloat16* __restrict__ Al,
                                                const __nv_bfloat16* __restrict__ Wh,
                                                const __nv_bfloat16* __restrict__ Wl,
                                                float* __restrict__ C, int T) {
    __shared__ __align__(128) char smem_buf[2 * STAGE_BYTES];
    const int t = threadIdx.x;
    const int wid = t >> 5, lane = t & 31;
    const int wm = wid & 3;            // m warp: 32 rows each
    const int wn = wid >> 2;           // n warp: 64 cols each
    const int rb = blockIdx.x * 128, jb = blockIdx.y * 128;
    const uint32_t sbase = smem_u32(smem_buf);

    // per-lane ldmatrix byte offsets within a stage
    // A x4: lanes 0-7 rows0-7 k0 | 8-15 rows8-15 k0 | 16-23 rows0-7 k8 | 24-31 rows8-15 k8
    const uint32_t a_off = (uint32_t)((wm * 32 + (lane & 15)) * 80 + (lane >> 4) * 16);
    // B x4 (non-trans; W is [N,K] row-major = col-major B):
    // lanes 0-7 n0-7 k0 | 8-15 n0-7 k8 | 16-23 n8-15 k0 | 24-31 n8-15 k8
    const uint32_t b_off = (uint32_t)((wn * 64 + (lane & 7) + ((lane >> 4) & 1) * 8) * 80
                                      + ((lane >> 3) & 1) * 16);

    float acc[2][8][4];
#pragma unroll
    for (int i = 0; i < 2; i++)
#pragma unroll
        for (int j = 0; j < 8; j++)
#pragma unroll
            for (int e = 0; e < 4; e++) acc[i][j][e] = 0.f;

    const int r01 = t >> 2;            // A row for this thread's 2 transfers? see below
    const int seg = t & 3;

    auto issue_stage = [&](int s, int ch) {
        const int term = ch >> 4, kc = ch & 15;
        const __nv_bfloat16* As = (term == 2) ? Al : Ah;
        const __nv_bfloat16* Ws = (term == 1) ? Wl : Wh;
        const __nv_bfloat16* Ag = As + (size_t)rb * HH + kc * 32;
        const __nv_bfloat16* Wg = Ws + (size_t)jb * HH + kc * 32;
        const uint32_t sA = sbase + s * STAGE_BYTES;
        const uint32_t sB = sA + 10240;
        // 512 x 16B for A (tid, tid+256), 512 for W (tid+512, tid+768)
        int rA0 = t >> 2;               // 0..63
        int rA1 = rA0 + 64;             // 64..127
        CP_ASYNC16(sA + rA0 * 80 + seg * 16,
                   (const char*)(Ag + (size_t)rA0 * HH) + seg * 16);
        CP_ASYNC16(sA + rA1 * 80 + seg * 16,
                   (const char*)(Ag + (size_t)rA1 * HH) + seg * 16);
        CP_ASYNC16(sB + rA0 * 80 + seg * 16,
                   (const char*)(Wg + (size_t)rA0 * HH) + seg * 16);
        CP_ASYNC16(sB + rA1 * 80 + seg * 16,
                   (const char*)(Wg + (size_t)rA1 * HH) + seg * 16);
    };

    issue_stage(0, 0);
    CP_COMMIT();

    for (int ch = 0; ch < 48; ch++) {
        if (ch + 1 < 48) {
            issue_stage((ch + 1) & 1, ch + 1);
            CP_COMMIT();
            CP_WAIT1();
        } else {
            CP_WAIT0();
        }
        __syncthreads();

        const int s = ch & 1;
        const uint32_t sA = sbase + s * STAGE_BYTES;
        const uint32_t sB = sA + 10240;
#pragma unroll
        for (int ks = 0; ks < 32; ks += 16) {
            uint32_t a[2][4], b[8][2];
#pragma unroll
            for (int mi = 0; mi < 2; mi++)
                ldsm4(a[mi], sA + a_off + mi * 16 * 80 + ks * 2);
#pragma unroll
            for (int j = 0; j < 4; j++) {
                uint32_t r4[4];
                ldsm4(r4, sB + b_off + j * 16 * 80 + ks * 2);
                b[2 * j][0] = r4[0];
                b[2 * j][1] = r4[1];
                b[2 * j + 1][0] = r4[2];
                b[2 * j + 1][1] = r4[3];
            }
#pragma unroll
            for (int mi = 0; mi < 2; mi++)
#pragma unroll
                for (int nj = 0; nj < 8; nj++)
                    mma16816(acc[mi][nj], a[mi], b[nj]);
        }
        __syncthreads();
    }

    // ---- epilogue ----
    const int g = lane >> 2, t4 = lane & 3;
#pragma unroll
    for (int mi = 0; mi < 2; mi++) {
        const int r0 = rb + wm * 32 + mi * 16 + g;
#pragma unroll
        for (int nj = 0; nj < 8; nj++) {
            const int jcol = jb + wn * 64 + nj * 8 + t4 * 2;
            if (MODE == 0) {
                float* d0 = C + (size_t)r0 * HH + jcol;
                float* d1 = C + (size_t)(r0 + 8) * HH + jcol;
                *(float2*)d0 = make_float2(acc[mi][nj][0], acc[mi][nj][1]);
                *(float2*)d1 = make_float2(acc[mi][nj][2], acc[mi][nj][3]);
            } else {
                const int head = (jcol >> 6) & 7, dd = jcol & 63;
                int b0 = r0 / T, tt0 = r0 % T;
                int b1 = (r0 + 8) / T, tt1 = (r0 + 8) % T;
                float* d0 = C + (((size_t)(b0 * 8 + head) * T + tt0) << 6) + dd;
                float* d1 = C + (((size_t)(b1 * 8 + head) * T + tt1) << 6) + dd;
                *(float2*)d0 = make_float2(acc[mi][nj][0], acc[mi][nj][1]);
                *(float2*)d1 = make_float2(acc[mi][nj][2], acc[mi][nj][3]);
            }
        }
    }
}

// ---------------------------------------------------------------------------
// Tiled banded attention (unchanged from R2; ~510us)
// ---------------------------------------------------------------------------
#define ATTN_SMEM_FLOATS (64*68*3 + 64*64 + 64*128)

__global__ void __launch_bounds__(256) attn2(const float* __restrict__ q,
                                             const float* __restrict__ k,
                                             const float* __restrict__ v,
                                             const float* __restrict__ pe,
                                             float* __restrict__ ao) {
    extern __shared__ float sm[];
    float* sQt = sm;
    float* sKt = sm + 64 * 68;
    float* sPs = sm + 64 * 68 * 2;
    float* sVs = sm + 64 * 68 * 3;
    float* sPe = sVs + 64 * 64;

    const int m0 = blockIdx.x * 64;
    const int bh = blockIdx.y;
    const int t = threadIdx.x;
    const int tx = t & 15;
    const int ty = t >> 4;
    const int r = t >> 2;
    const int seg = t & 3;

    {
        const float* qg = q + ((size_t)bh * MM + m0) * DD + (size_t)r * DD;
#pragma unroll
        for (int w = 0; w < 4; w++) {
            int d0 = seg * 16 + w * 4;
            float4 val = *(const float4*)(qg + d0);
            sQt[(d0 + 0) * 68 + r] = val.x;
            sQt[(d0 + 1) * 68 + r] = val.y;
            sQt[(d0 + 2) * 68 + r] = val.z;
            sQt[(d0 + 3) * 68 + r] = val.w;
        }
    }

    float o[4][4] = {};
    float rmax[4], rsum[4];
#pragma unroll
    for (int i = 0; i < 4; i++) { rmax[i] = -3.0e38f; rsum[i] = 0.f; }

    const int pshift = 61 + 4 * (tx - ty);

    for (int c = 0; c < 17; c++) {
        __syncthreads();
        {
            const size_t bsz = ((size_t)bh * NN + m0 + c * 64 + r) * DD;
            const float* kg = k + bsz;
            const float* vg = v + bsz;
#pragma unroll
            for (int w = 0; w < 4; w++) {
                int d0 = seg * 16 + w * 4;
                float4 kv4 = *(const float4*)(kg + d0);
                sKt[(d0 + 0) * 68 + r] = kv4.x;
                sKt[(d0 + 1) * 68 + r] = kv4.y;
                sKt[(d0 + 2) * 68 + r] = kv4.z;
                sKt[(d0 + 3) * 68 + r] = kv4.w;
                float4 vv4 = *(const float4*)(vg + d0);
                *(float4*)&sVs[r * 64 + d0] = vv4;
            }
        }
        {
            int lbase = (c - 1) * 64;
#pragma unroll
            for (int it = 0; it < 8; it++) {
                int idx = t + it * 256;
                int d = idx >> 5;
                int col = (idx & 31) << 2;
                int gl = lbase + col;
                float4 pv;
                if (gl >= 0 && gl < LL) pv = *(const float4*)(pe + (size_t)d * LL + gl);
                else pv = make_float4(0.f, 0.f, 0.f, 0.f);
                *(float4*)&sPe[d * 128 + col] = pv;
            }
        }
        __syncthreads();

        float acc[4][4] = {};
#pragma unroll 2
        for (int d = 0; d < 64; d++) {
            const float4 qv = *(const float4*)&sQt[d * 68 + (ty << 2)];
            const float4 kv = *(const float4*)&sKt[d * 68 + (tx << 2)];
            const float* pb = &sPe[d * 128 + pshift];
            float pe7[7];
#pragma unroll
            for (int s = 0; s < 7; s++) pe7[s] = pb[s];
            const float qa[4] = {qv.x, qv.y, qv.z, qv.w};
            const float ka[4] = {kv.x, kv.y, kv.z, kv.w};
#pragma unroll
            for (int i = 0; i < 4; i++)
#pragma unroll
                for (int j = 0; j < 4; j++) {
                    acc[i][j] += qa[i] * ka[j];
                    acc[i][j] += qa[i] * pe7[3 + j - i];
                }
        }
#pragma unroll
        for (int i = 0; i < 4; i++)
#pragma unroll
            for (int j = 0; j < 4; j++) acc[i][j] *= 0.125f;

        if (c == 0 || c == 16) {
#pragma unroll
            for (int i = 0; i < 4; i++)
#pragma unroll
                for (int j = 0; j < 4; j++) {
                    int lrel = 64 * c + (tx * 4 + j) - (ty * 4 + i);
                    if (lrel < 0 || lrel >= LL) acc[i][j] = -1.0e30f;
                }
        }

        float p[4][4];
#pragma unroll
        for (int i = 0; i < 4; i++) {
            float mx = fmaxf(fmaxf(acc[i][0], acc[i][1]), fmaxf(acc[i][2], acc[i][3]));
#pragma unroll
            for (int off = 8; off > 0; off >>= 1)
                mx = fmaxf(mx, __shfl_xor_sync(0xffffffffu, mx, off, 16));
            float nm = fmaxf(rmax[i], mx);
            float corr = __expf(rmax[i] - nm);
            float ls = 0.f;
#pragma unroll
            for (int j = 0; j < 4; j++) {
                p[i][j] = __expf(acc[i][j] - nm);
                ls += p[i][j];
            }
#pragma unroll
            for (int off = 8; off > 0; off >>= 1)
                ls += __shfl_xor_sync(0xffffffffu, ls, off, 16);
            rsum[i] = rsum[i] * corr + ls;
            rmax[i] = nm;
#pragma unroll
            for (int j = 0; j < 4; j++) o[i][j] *= corr;
        }

#pragma unroll
        for (int i = 0; i < 4; i++) {
            float4 pv = make_float4(p[i][0], p[i][1], p[i][2], p[i][3]);
            *(float4*)&sPs[(ty * 4 + i) * 68 + tx * 4] = pv;
        }
        __syncthreads();

#pragma unroll 4
        for (int nl = 0; nl < 64; nl++) {
            float4 vv = *(const float4*)&sVs[nl * 64 + (tx << 2)];
            float pa[4];
#pragma unroll
            for (int i = 0; i < 4; i++) pa[i] = sPs[(ty * 4 + i) * 68 + nl];
            const float va[4] = {vv.x, vv.y, vv.z, vv.w};
#pragma unroll
            for (int i = 0; i < 4; i++)
#pragma unroll
                for (int j = 0; j < 4; j++) o[i][j] += pa[i] * va[j];
        }
    }

    const int b = bh >> 3, h = bh & 7;
#pragma unroll
    for (int i = 0; i < 4; i++) {
        float inv = 1.f / rsum[i];
        int m = m0 + ty * 4 + i;
        float4 ov = make_float4(o[i][0] * inv, o[i][1] * inv, o[i][2] * inv, o[i][3] * inv);
        *(float4*)&ao[((size_t)(b * MM + m) * HH) + h * 64 + tx * 4] = ov;
    }
}

// ---------------------------------------------------------------------------
extern "C" void kernel_launch(void* const* d_in, const int* in_sizes, int n_in,
                              void* d_out, int out_size) {
    const float* query  = (const float*)d_in[0];
    const float* key    = (const float*)d_in[1];
    const float* value  = (const float*)d_in[2];
    const float* key_pe = (const float*)d_in[3];
    const float* Wq     = (const float*)d_in[4];
    const float* Wk     = (const float*)d_in[5];
    const float* Wv     = (const float*)d_in[6];
    const float* Wo     = (const float*)d_in[7];
    float* out = (float*)d_out;

    float *qb, *kb, *vb, *aob;
    cudaGetSymbolAddress((void**)&qb, g_q);
    cudaGetSymbolAddress((void**)&kb, g_k);
    cudaGetSymbolAddress((void**)&vb, g_v);
    cudaGetSymbolAddress((void**)&aob, g_ao);
    __nv_bfloat16 *qh, *ql, *kh, *kl, *vh, *vl, *aoh, *aol, *wh, *wl;
    cudaGetSymbolAddress((void**)&qh, g_qh);
    cudaGetSymbolAddress((void**)&ql, g_ql);
    cudaGetSymbolAddress((void**)&kh, g_kh);
    cudaGetSymbolAddress((void**)&kl, g_kl);
    cudaGetSymbolAddress((void**)&vh, g_vh);
    cudaGetSymbolAddress((void**)&vl, g_vl);
    cudaGetSymbolAddress((void**)&aoh, g_aoh);
    cudaGetSymbolAddress((void**)&aol, g_aol);
    cudaGetSymbolAddress((void**)&wh, g_wh);
    cudaGetSymbolAddress((void**)&wl, g_wl);

    static bool attr_set = false;
    if (!attr_set) {
        cudaFuncSetAttribute(attn2, cudaFuncAttributeMaxDynamicSharedMemorySize,
                             ATTN_SMEM_FLOATS * sizeof(float));
        attr_set = true;
    }

    // splits
    split_bf16<<<(BB * MM * HH / 4 + 255) / 256, 256>>>(query, qh, ql, BB * MM * HH / 4);
    split_bf16<<<(BB * NN * HH / 4 + 255) / 256, 256>>>(key, kh, kl, BB * NN * HH / 4);
    split_bf16<<<(BB * NN * HH / 4 + 255) / 256, 256>>>(value, vh, vl, BB * NN * HH / 4);
    split_w4<<<dim3(HH * HH / 4 / 256, 4), 256>>>(Wq, Wk, Wv, Wo, wh, wl);

    // projections (HMMA, head scatter)
    gemm_mma<1><<<dim3(BB * MM / 128, 4), 256>>>(qh, ql, wh + 0 * HH * HH,
                                                 wl + 0 * HH * HH, qb, MM);
    gemm_mma<1><<<dim3(BB * NN / 128, 4), 256>>>(kh, kl, wh + 1 * HH * HH,
                                                 wl + 1 * HH * HH, kb, NN);
    gemm_mma<1><<<dim3(BB * NN / 128, 4), 256>>>(vh, vl, wh + 2 * HH * HH,
                                                 wl + 2 * HH * HH, vb, NN);

    // attention
    attn2<<<dim3(MM / 64, 64), 256, ATTN_SMEM_FLOATS * sizeof(float)>>>(
        qb, kb, vb, key_pe, aob);

    // output projection
    split_bf16<<<(BB * MM * HH / 4 + 255) / 256, 256>>>(aob, aoh, aol, BB * MM * HH / 4);
    gemm_mma<0><<<dim3(BB * MM / 128, 4), 256>>>(aoh, aol, wh + 3 * HH * HH,
                                                 wl + 3 * HH * HH, out, MM);
}

// round 6
// speedup vs baseline: 7.4217x; 1.6916x over previous
#include <cuda_runtime.h>
#include <cuda_bf16.h>
#include <cstdint>

// Problem constants
#define BB 8
#define MM 512
#define HH 512
#define DD 64
#define LL 1024
#define NN 1536   // M + L

// ---------------------------------------------------------------------------
// Scratch (device globals: allocation-free rule)
// ---------------------------------------------------------------------------
__device__ __nv_bfloat16 g_iqh[BB * MM * HH], g_iql[BB * MM * HH];
__device__ __nv_bfloat16 g_ikh[BB * NN * HH], g_ikl[BB * NN * HH];
__device__ __nv_bfloat16 g_ivh[BB * NN * HH], g_ivl[BB * NN * HH];
__device__ __nv_bfloat16 g_hqh[64 * MM * DD], g_hql[64 * MM * DD];
__device__ __nv_bfloat16 g_hkh[64 * NN * DD], g_hkl[64 * NN * DD];
__device__ __nv_bfloat16 g_hvh[64 * NN * DD], g_hvl[64 * NN * DD];
__device__ __nv_bfloat16 g_aoh[BB * MM * HH], g_aol[BB * MM * HH];
__device__ __nv_bfloat16 g_wh[4 * HH * HH], g_wl[4 * HH * HH];
__device__ __nv_bfloat16 g_peh[LL * DD], g_pel[LL * DD];
__device__ float g_sp[64 * MM * LL];

// ---------------------------------------------------------------------------
// PTX helpers (sm_80-era only; valid for compute_103 PTX target)
// ---------------------------------------------------------------------------
__device__ __forceinline__ uint32_t smem_u32(const void* p) {
    uint32_t a;
    asm("{ .reg .u64 t; cvta.to.shared.u64 t, %1; cvt.u32.u64 %0, t; }"
        : "=r"(a) : "l"(p));
    return a;
}
__device__ __forceinline__ void ldsm4(uint32_t* r, uint32_t a) {
    asm volatile("ldmatrix.sync.aligned.m8n8.x4.shared.b16 {%0,%1,%2,%3}, [%4];"
                 : "=r"(r[0]), "=r"(r[1]), "=r"(r[2]), "=r"(r[3]) : "r"(a));
}
__device__ __forceinline__ void ldsm4t(uint32_t* r, uint32_t a) {
    asm volatile("ldmatrix.sync.aligned.m8n8.x4.trans.shared.b16 {%0,%1,%2,%3}, [%4];"
                 : "=r"(r[0]), "=r"(r[1]), "=r"(r[2]), "=r"(r[3]) : "r"(a));
}
__device__ __forceinline__ void mma16816(float* c, const uint32_t* a,
                                         const uint32_t* b) {
    asm volatile(
        "mma.sync.aligned.m16n8k16.row.col.f32.bf16.bf16.f32 "
        "{%0,%1,%2,%3}, {%4,%5,%6,%7}, {%8,%9}, {%0,%1,%2,%3};"
        : "+f"(c[0]), "+f"(c[1]), "+f"(c[2]), "+f"(c[3])
        : "r"(a[0]), "r"(a[1]), "r"(a[2]), "r"(a[3]), "r"(b[0]), "r"(b[1]));
}
__device__ __forceinline__ uint32_t packbf(float a, float b) {
    __nv_bfloat162 h = __floats2bfloat162_rn(a, b);
    return *(uint32_t*)&h;
}
__device__ __forceinline__ uint32_t packbf_lo(float a, float b) {
    float ra = a - __bfloat162float(__float2bfloat16(a));
    float rb = b - __bfloat162float(__float2bfloat16(b));
    return packbf(ra, rb);
}

// ---------------------------------------------------------------------------
// Split kernels
// ---------------------------------------------------------------------------
__global__ void __launch_bounds__(256) split_bf16(const float* __restrict__ x,
                                                  __nv_bfloat16* __restrict__ hi,
                                                  __nv_bfloat16* __restrict__ lo,
                                                  int n4) {
    int i = blockIdx.x * 256 + threadIdx.x;
    if (i >= n4) return;
    float4 v = ((const float4*)x)[i];
    __nv_bfloat16 h0 = __float2bfloat16(v.x), h1 = __float2bfloat16(v.y);
    __nv_bfloat16 h2 = __float2bfloat16(v.z), h3 = __float2bfloat16(v.w);
    ((__nv_bfloat162*)hi)[2 * i]     = __nv_bfloat162(h0, h1);
    ((__nv_bfloat162*)hi)[2 * i + 1] = __nv_bfloat162(h2, h3);
    ((__nv_bfloat162*)lo)[2 * i] = __nv_bfloat162(
        __float2bfloat16(v.x - __bfloat162float(h0)),
        __float2bfloat16(v.y - __bfloat162float(h1)));
    ((__nv_bfloat162*)lo)[2 * i + 1] = __nv_bfloat162(
        __float2bfloat16(v.z - __bfloat162float(h2)),
        __float2bfloat16(v.w - __bfloat162float(h3)));
}

__global__ void __launch_bounds__(256) split_w4(const float* __restrict__ w0,
                                                const float* __restrict__ w1,
                                                const float* __restrict__ w2,
                                                const float* __restrict__ w3,
                                                __nv_bfloat16* __restrict__ hi,
                                                __nv_bfloat16* __restrict__ lo) {
    const float* src = (blockIdx.y == 0) ? w0 : (blockIdx.y == 1) ? w1
                     : (blockIdx.y == 2) ? w2 : w3;
    int i = blockIdx.x * 256 + threadIdx.x;
    size_t base2 = (size_t)blockIdx.y * (HH * HH / 2);
    float4 v = ((const float4*)src)[i];
    __nv_bfloat16 h0 = __float2bfloat16(v.x), h1 = __float2bfloat16(v.y);
    __nv_bfloat16 h2 = __float2bfloat16(v.z), h3 = __float2bfloat16(v.w);
    ((__nv_bfloat162*)hi)[base2 + 2 * i]     = __nv_bfloat162(h0, h1);
    ((__nv_bfloat162*)hi)[base2 + 2 * i + 1] = __nv_bfloat162(h2, h3);
    ((__nv_bfloat162*)lo)[base2 + 2 * i] = __nv_bfloat162(
        __float2bfloat16(v.x - __bfloat162float(h0)),
        __float2bfloat16(v.y - __bfloat162float(h1)));
    ((__nv_bfloat162*)lo)[base2 + 2 * i + 1] = __nv_bfloat162(
        __float2bfloat16(v.z - __bfloat162float(h2)),
        __float2bfloat16(v.w - __bfloat162float(h3)));
}

// pe [64 d][1024 l] fp32 -> transposed bf16 hi/lo [l][d]
__global__ void __launch_bounds__(256) split_pe(const float* __restrict__ pe,
                                                __nv_bfloat16* __restrict__ ph,
                                                __nv_bfloat16* __restrict__ pl) {
    int i = blockIdx.x * 256 + threadIdx.x;
    int d = i >> 10, l = i & 1023;
    float v = pe[i];
    __nv_bfloat16 h = __float2bfloat16(v);
    ph[l * 64 + d] = h;
    pl[l * 64 + d] = __float2bfloat16(v - __bfloat162float(h));
}

// ---------------------------------------------------------------------------
// HMMA GEMM: C[r,j] = sum_h A[r,h]*W[j,h] via 3-term bf16 split.
// MODE 0: fp32 row-major. MODE 1: head scatter, 1/8 scale, bf16 hi/lo.
// MODE 2: head scatter, bf16 hi/lo.
// ---------------------------------------------------------------------------
#define STAGE_BYTES 20480

template <int MODE>
__global__ void __launch_bounds__(256) gemm_mma(const __nv_bfloat16* __restrict__ Ah,
                                                const __nv_bfloat16* __restrict__ Al,
                                                const __nv_bfloat16* __restrict__ Wh,
                                                const __nv_bfloat16* __restrict__ Wl,
                                                float* __restrict__ C,
                                                __nv_bfloat16* __restrict__ Chi,
                                                __nv_bfloat16* __restrict__ Clo,
                                                int T) {
    __shared__ __align__(128) char smem_buf[2 * STAGE_BYTES];
    const int t = threadIdx.x;
    const int wid = t >> 5, lane = t & 31;
    const int wm = wid & 3, wn = wid >> 2;
    const int rb = blockIdx.x * 128, jb = blockIdx.y * 128;
    const uint32_t sbase = smem_u32(smem_buf);

    const uint32_t a_off = (uint32_t)((wm * 32 + (lane & 15)) * 80 + (lane >> 4) * 16);
    const uint32_t b_off = (uint32_t)((wn * 64 + (lane & 7) + ((lane >> 4) & 1) * 8) * 80
                                      + ((lane >> 3) & 1) * 16);

    float acc[2][8][4];
#pragma unroll
    for (int i = 0; i < 2; i++)
#pragma unroll
        for (int j = 0; j < 8; j++)
#pragma unroll
            for (int e = 0; e < 4; e++) acc[i][j][e] = 0.f;

    const int seg = t & 3;

    auto issue_stage = [&](int s, int ch) {
        const int term = ch >> 4, kc = ch & 15;
        const __nv_bfloat16* As = (term == 2) ? Al : Ah;
        const __nv_bfloat16* Ws = (term == 1) ? Wl : Wh;
        const __nv_bfloat16* Ag = As + (size_t)rb * HH + kc * 32;
        const __nv_bfloat16* Wg = Ws + (size_t)jb * HH + kc * 32;
        const uint32_t sA = sbase + s * STAGE_BYTES;
        const uint32_t sB = sA + 10240;
        int rA0 = t >> 2, rA1 = rA0 + 64;
        asm volatile("cp.async.cg.shared.global [%0], [%1], 16;" ::
                     "r"(sA + rA0 * 80 + seg * 16),
                     "l"((const char*)(Ag + (size_t)rA0 * HH) + seg * 16) : "memory");
        asm volatile("cp.async.cg.shared.global [%0], [%1], 16;" ::
                     "r"(sA + rA1 * 80 + seg * 16),
                     "l"((const char*)(Ag + (size_t)rA1 * HH) + seg * 16) : "memory");
        asm volatile("cp.async.cg.shared.global [%0], [%1], 16;" ::
                     "r"(sB + rA0 * 80 + seg * 16),
                     "l"((const char*)(Wg + (size_t)rA0 * HH) + seg * 16) : "memory");
        asm volatile("cp.async.cg.shared.global [%0], [%1], 16;" ::
                     "r"(sB + rA1 * 80 + seg * 16),
                     "l"((const char*)(Wg + (size_t)rA1 * HH) + seg * 16) : "memory");
    };

    issue_stage(0, 0);
    asm volatile("cp.async.commit_group;" ::: "memory");

    for (int ch = 0; ch < 48; ch++) {
        if (ch + 1 < 48) {
            issue_stage((ch + 1) & 1, ch + 1);
            asm volatile("cp.async.commit_group;" ::: "memory");
            asm volatile("cp.async.wait_group 1;" ::: "memory");
        } else {
            asm volatile("cp.async.wait_group 0;" ::: "memory");
        }
        __syncthreads();

        const int s = ch & 1;
        const uint32_t sA = sbase + s * STAGE_BYTES;
        const uint32_t sB = sA + 10240;
#pragma unroll
        for (int ks = 0; ks < 32; ks += 16) {
            uint32_t a[2][4], b[8][2];
#pragma unroll
            for (int mi = 0; mi < 2; mi++)
                ldsm4(a[mi], sA + a_off + mi * 16 * 80 + ks * 2);
#pragma unroll
            for (int j = 0; j < 4; j++) {
                uint32_t r4[4];
                ldsm4(r4, sB + b_off + j * 16 * 80 + ks * 2);
                b[2 * j][0] = r4[0]; b[2 * j][1] = r4[1];
                b[2 * j + 1][0] = r4[2]; b[2 * j + 1][1] = r4[3];
            }
#pragma unroll
            for (int mi = 0; mi < 2; mi++)
#pragma unroll
                for (int nj = 0; nj < 8; nj++)
                    mma16816(acc[mi][nj], a[mi], b[nj]);
        }
        __syncthreads();
    }

    const int g = lane >> 2, t4 = lane & 3;
    const float scale = (MODE == 1) ? 0.125f : 1.0f;
#pragma unroll
    for (int mi = 0; mi < 2; mi++) {
        const int r0 = rb + wm * 32 + mi * 16 + g;
#pragma unroll
        for (int nj = 0; nj < 8; nj++) {
            const int jcol = jb + wn * 64 + nj * 8 + t4 * 2;
            float v0 = acc[mi][nj][0] * scale, v1 = acc[mi][nj][1] * scale;
            float v2 = acc[mi][nj][2] * scale, v3 = acc[mi][nj][3] * scale;
            if (MODE == 0) {
                *(float2*)(C + (size_t)r0 * HH + jcol) = make_float2(v0, v1);
                *(float2*)(C + (size_t)(r0 + 8) * HH + jcol) = make_float2(v2, v3);
            } else {
                const int head = (jcol >> 6) & 7, dd = jcol & 63;
                int b0 = r0 / T, tt0 = r0 % T;
                int b1 = (r0 + 8) / T, tt1 = (r0 + 8) % T;
                size_t o0 = (((size_t)(b0 * 8 + head) * T + tt0) << 6) + dd;
                size_t o1 = (((size_t)(b1 * 8 + head) * T + tt1) << 6) + dd;
                *(uint32_t*)(Chi + o0) = packbf(v0, v1);
                *(uint32_t*)(Chi + o1) = packbf(v2, v3);
                *(uint32_t*)(Clo + o0) = packbf_lo(v0, v1);
                *(uint32_t*)(Clo + o1) = packbf_lo(v2, v3);
            }
        }
    }
}

// ---------------------------------------------------------------------------
// Spos GEMM: sp[bh][m][l] = qhat[bh][m][:] . pe_t[l][:] (3-term split).
// Tile 128m x 128l, K=64. 8 warps (4m x 2l).
// ---------------------------------------------------------------------------
__global__ void __launch_bounds__(256) gemm_sp(const __nv_bfloat16* __restrict__ qhh,
                                               const __nv_bfloat16* __restrict__ qhl,
                                               const __nv_bfloat16* __restrict__ peh,
                                               const __nv_bfloat16* __restrict__ pel,
                                               float* __restrict__ spout) {
    __shared__ __align__(16) char sm[2 * 18432];
    const int t = threadIdx.x;
    const int wid = t >> 5, lane = t & 31;
    const int wm = wid & 3, wn = wid >> 2;
    const int mb = blockIdx.x, lb = blockIdx.y, bh = blockIdx.z;
    const uint32_t sA = smem_u32(sm), sB = sA + 18432;

    float acc[2][8][4];
#pragma unroll
    for (int i = 0; i < 2; i++)
#pragma unroll
        for (int j = 0; j < 8; j++)
#pragma unroll
            for (int e = 0; e < 4; e++) acc[i][j][e] = 0.f;

    // FIXED staging: full 128B rows (row = id>>3, seg = id&7)
    auto stageA = [&](const __nv_bfloat16* src) {
#pragma unroll
        for (int e = 0; e < 4; e++) {
            int id = t + e * 256, row = id >> 3, seg = id & 7;
            *(uint4*)(sm + row * 144 + seg * 16) =
                *(const uint4*)(src + ((size_t)bh * MM + mb * 128 + row) * 64 + seg * 8);
        }
    };
    auto stageB = [&](const __nv_bfloat16* src) {
#pragma unroll
        for (int e = 0; e < 4; e++) {
            int id = t + e * 256, row = id >> 3, seg = id & 7;
            *(uint4*)(sm + 18432 + row * 144 + seg * 16) =
                *(const uint4*)(src + ((size_t)(lb * 128 + row)) * 64 + seg * 8);
        }
    };
    const uint32_t aoff = sA + (wm * 32 + (lane & 15)) * 144 + (lane >> 4) * 16;
    const uint32_t boff = sB + (wn * 64 + (lane & 7) + ((lane >> 4) & 1) * 8) * 144
                        + ((lane >> 3) & 1) * 16;
    auto domma = [&]() {
#pragma unroll
        for (int ks = 0; ks < 4; ks++) {
            uint32_t a0[4], a1[4];
            ldsm4(a0, aoff + ks * 32);
            ldsm4(a1, aoff + 16 * 144 + ks * 32);
#pragma unroll
            for (int nb = 0; nb < 4; nb++) {
                uint32_t r4[4];
                ldsm4(r4, boff + nb * 16 * 144 + ks * 32);
                mma16816(acc[0][2 * nb], a0, r4);
                mma16816(acc[0][2 * nb + 1], a0, r4 + 2);
                mma16816(acc[1][2 * nb], a1, r4);
                mma16816(acc[1][2 * nb + 1], a1, r4 + 2);
            }
        }
    };

    stageA(qhh); stageB(peh);
    __syncthreads(); domma(); __syncthreads();
    stageA(qhl);
    __syncthreads(); domma(); __syncthreads();
    stageA(qhh); stageB(pel);
    __syncthreads(); domma();

    const int g = lane >> 2, t4 = lane & 3;
#pragma unroll
    for (int mi = 0; mi < 2; mi++) {
        int m = mb * 128 + wm * 32 + mi * 16 + g;
#pragma unroll
        for (int nj = 0; nj < 8; nj++) {
            int l = lb * 128 + wn * 64 + nj * 8 + t4 * 2;
            float* d0 = spout + ((size_t)bh * MM + m) * 1024 + l;
            *(float2*)d0 = make_float2(acc[mi][nj][0], acc[mi][nj][1]);
            *(float2*)(d0 + 8 * 1024) = make_float2(acc[mi][nj][2], acc[mi][nj][3]);
        }
    }
}

// ---------------------------------------------------------------------------
// HMMA flash banded attention. m-tile 64, 4 warps (16 rows each), 17 chunks.
// ---------------------------------------------------------------------------
#define SQH 0
#define SQL 9216
#define SKH 18432
#define SKL 27648
#define SVH 36864
#define SVL 46080
#define SSP 55296
#define ATTN_SMEM (SSP + 64 * 128 * 4)   // 88064

__global__ void __launch_bounds__(128) attn3(
    const __nv_bfloat16* __restrict__ qhh, const __nv_bfloat16* __restrict__ qhl,
    const __nv_bfloat16* __restrict__ khh, const __nv_bfloat16* __restrict__ khl,
    const __nv_bfloat16* __restrict__ vhh, const __nv_bfloat16* __restrict__ vhl,
    const float* __restrict__ sp,
    __nv_bfloat16* __restrict__ aoh, __nv_bfloat16* __restrict__ aol) {
    extern __shared__ __align__(16) char smc[];
    const uint32_t sb = smem_u32(smc);
    float* sSpf = (float*)(smc + SSP);

    const int m0 = blockIdx.x * 64;
    const int bh = blockIdx.y;
    const int t = threadIdx.x, lane = t & 31, wm = t >> 5;
    const int g = lane >> 2, t4 = lane & 3;
    const int i0 = wm * 16 + g;

    // ---- stage Q (FIXED: full rows) ----
#pragma unroll
    for (int e = 0; e < 4; e++) {
        int id = t + e * 128, row = id >> 3, seg = id & 7;
        size_t srow = ((size_t)bh * MM + m0 + row) * 64 + seg * 8;
        uint32_t dst = row * 144 + seg * 16;
        *(uint4*)(smc + SQH + dst) = *(const uint4*)(qhh + srow);
        *(uint4*)(smc + SQL + dst) = *(const uint4*)(qhl + srow);
    }
    __syncthreads();

    uint32_t qa_h[4][4], qa_l[4][4];
    {
        const uint32_t arel = (wm * 16 + (lane & 15)) * 144 + (lane >> 4) * 16;
#pragma unroll
        for (int ks = 0; ks < 4; ks++) {
            ldsm4(qa_h[ks], sb + SQH + arel + ks * 32);
            ldsm4(qa_l[ks], sb + SQL + arel + ks * 32);
        }
    }

    const uint32_t bKrel = ((lane & 7) + ((lane >> 4) & 1) * 8) * 144
                         + ((lane >> 3) & 1) * 16;
    const uint32_t bVrel = (lane & 15) * 144 + (lane >> 4) * 16;

    float o[8][4];
#pragma unroll
    for (int j = 0; j < 8; j++)
#pragma unroll
        for (int e = 0; e < 4; e++) o[j][e] = 0.f;
    float rmax0 = -1e30f, rmax1 = -1e30f, rsum0 = 0.f, rsum1 = 0.f;

    for (int c = 0; c < 17; c++) {
        __syncthreads();
        // ---- stage K, V hi/lo (FIXED: full rows) ----
        {
            const size_t nbase = (size_t)bh * NN + m0 + c * 64;
#pragma unroll
            for (int e = 0; e < 4; e++) {
                int id = t + e * 128, row = id >> 3, seg = id & 7;
                size_t srow = (nbase + row) * 64 + seg * 8;
                uint32_t dst = row * 144 + seg * 16;
                *(uint4*)(smc + SKH + dst) = *(const uint4*)(khh + srow);
                *(uint4*)(smc + SKL + dst) = *(const uint4*)(khl + srow);
                *(uint4*)(smc + SVH + dst) = *(const uint4*)(vhh + srow);
                *(uint4*)(smc + SVL + dst) = *(const uint4*)(vhl + srow);
            }
        }
        // ---- stage Spos slice: cols [64(c-1), 64(c-1)+128) ----
        {
            const int lbase = (c - 1) * 64;
#pragma unroll
            for (int e = 0; e < 16; e++) {
                int id = t + e * 128, row = id >> 5, q4 = id & 31;
                int gcol = lbase + q4 * 4;
                float4 v;
                if (gcol >= 0 && gcol < 1024)
                    v = *(const float4*)(sp + ((size_t)bh * MM + m0 + row) * 1024 + gcol);
                else
                    v = make_float4(0.f, 0.f, 0.f, 0.f);
                *(float4*)&sSpf[row * 128 + q4 * 4] = v;
            }
        }
        __syncthreads();

        // ---- S = qhat . k (3-term) ----
        float s[8][4];
#pragma unroll
        for (int j = 0; j < 8; j++)
#pragma unroll
            for (int e = 0; e < 4; e++) s[j][e] = 0.f;
#pragma unroll
        for (int ks = 0; ks < 4; ks++) {
#pragma unroll
            for (int nb = 0; nb < 4; nb++) {
                uint32_t rh[4], rl[4];
                ldsm4(rh, sb + SKH + bKrel + nb * 16 * 144 + ks * 32);
                ldsm4(rl, sb + SKL + bKrel + nb * 16 * 144 + ks * 32);
                mma16816(s[2 * nb],     qa_h[ks], rh);
                mma16816(s[2 * nb + 1], qa_h[ks], rh + 2);
                mma16816(s[2 * nb],     qa_l[ks], rh);
                mma16816(s[2 * nb + 1], qa_l[ks], rh + 2);
                mma16816(s[2 * nb],     qa_h[ks], rl);
                mma16816(s[2 * nb + 1], qa_h[ks], rl + 2);
            }
        }

        // ---- add Spos + band mask ----
#pragma unroll
        for (int nj = 0; nj < 8; nj++) {
            int j0 = nj * 8 + t4 * 2;
            s[nj][0] += sSpf[i0 * 128 + (j0 - i0 + 64)];
            s[nj][1] += sSpf[i0 * 128 + (j0 - i0 + 65)];
            s[nj][2] += sSpf[(i0 + 8) * 128 + (j0 - i0 + 56)];
            s[nj][3] += sSpf[(i0 + 8) * 128 + (j0 - i0 + 57)];
        }
        if (c == 0) {
#pragma unroll
            for (int nj = 0; nj < 8; nj++) {
                int j0 = nj * 8 + t4 * 2;
                if (j0 < i0) s[nj][0] = -1e30f;
                if (j0 + 1 < i0) s[nj][1] = -1e30f;
                if (j0 < i0 + 8) s[nj][2] = -1e30f;
                if (j0 + 1 < i0 + 8) s[nj][3] = -1e30f;
            }
        } else if (c == 16) {
#pragma unroll
            for (int nj = 0; nj < 8; nj++) {
                int j0 = nj * 8 + t4 * 2;
                if (j0 >= i0) s[nj][0] = -1e30f;
                if (j0 + 1 >= i0) s[nj][1] = -1e30f;
                if (j0 >= i0 + 8) s[nj][2] = -1e30f;
                if (j0 + 1 >= i0 + 8) s[nj][3] = -1e30f;
            }
        }

        // ---- online softmax ----
        {
            float mx0 = -1e30f, mx1 = -1e30f;
#pragma unroll
            for (int nj = 0; nj < 8; nj++) {
                mx0 = fmaxf(mx0, fmaxf(s[nj][0], s[nj][1]));
                mx1 = fmaxf(mx1, fmaxf(s[nj][2], s[nj][3]));
            }
            mx0 = fmaxf(mx0, __shfl_xor_sync(0xffffffffu, mx0, 1));
            mx0 = fmaxf(mx0, __shfl_xor_sync(0xffffffffu, mx0, 2));
            mx1 = fmaxf(mx1, __shfl_xor_sync(0xffffffffu, mx1, 1));
            mx1 = fmaxf(mx1, __shfl_xor_sync(0xffffffffu, mx1, 2));
            float nm0 = fmaxf(rmax0, mx0), nm1 = fmaxf(rmax1, mx1);
            float corr0 = __expf(rmax0 - nm0), corr1 = __expf(rmax1 - nm1);
            rmax0 = nm0; rmax1 = nm1;
            float ls0 = 0.f, ls1 = 0.f;
#pragma unroll
            for (int nj = 0; nj < 8; nj++) {
                s[nj][0] = __expf(s[nj][0] - nm0);
                s[nj][1] = __expf(s[nj][1] - nm0);
                s[nj][2] = __expf(s[nj][2] - nm1);
                s[nj][3] = __expf(s[nj][3] - nm1);
                ls0 += s[nj][0] + s[nj][1];
                ls1 += s[nj][2] + s[nj][3];
            }
            ls0 += __shfl_xor_sync(0xffffffffu, ls0, 1);
            ls0 += __shfl_xor_sync(0xffffffffu, ls0, 2);
            ls1 += __shfl_xor_sync(0xffffffffu, ls1, 1);
            ls1 += __shfl_xor_sync(0xffffffffu, ls1, 2);
            rsum0 = rsum0 * corr0 + ls0;
            rsum1 = rsum1 * corr1 + ls1;
#pragma unroll
            for (int j = 0; j < 8; j++) {
                o[j][0] *= corr0; o[j][1] *= corr0;
                o[j][2] *= corr1; o[j][3] *= corr1;
            }
        }

        // ---- O += P . V (3-term, P split in registers) ----
#pragma unroll
        for (int ks = 0; ks < 4; ks++) {
            uint32_t pah[4], pal[4];
            pah[0] = packbf(s[2 * ks][0], s[2 * ks][1]);
            pah[1] = packbf(s[2 * ks][2], s[2 * ks][3]);
            pah[2] = packbf(s[2 * ks + 1][0], s[2 * ks + 1][1]);
            pah[3] = packbf(s[2 * ks + 1][2], s[2 * ks + 1][3]);
            pal[0] = packbf_lo(s[2 * ks][0], s[2 * ks][1]);
            pal[1] = packbf_lo(s[2 * ks][2], s[2 * ks][3]);
            pal[2] = packbf_lo(s[2 * ks + 1][0], s[2 * ks + 1][1]);
            pal[3] = packbf_lo(s[2 * ks + 1][2], s[2 * ks + 1][3]);
#pragma unroll
            for (int dj = 0; dj < 4; dj++) {
                uint32_t rh[4], rl[4];
                ldsm4t(rh, sb + SVH + bVrel + ks * 16 * 144 + dj * 32);
                ldsm4t(rl, sb + SVL + bVrel + ks * 16 * 144 + dj * 32);
                mma16816(o[2 * dj],     pah, rh);
                mma16816(o[2 * dj + 1], pah, rh + 2);
                mma16816(o[2 * dj],     pal, rh);
                mma16816(o[2 * dj + 1], pal, rh + 2);
                mma16816(o[2 * dj],     pah, rl);
                mma16816(o[2 * dj + 1], pah, rl + 2);
            }
        }
    }

    // ---- epilogue ----
    {
        float inv0 = 1.f / rsum0, inv1 = 1.f / rsum1;
        int b = bh >> 3, hd = bh & 7;
        int mr = m0 + i0;
#pragma unroll
        for (int nj = 0; nj < 8; nj++) {
            int col = hd * 64 + nj * 8 + t4 * 2;
            size_t idx0 = ((size_t)(b * MM + mr) * HH) + col;
            size_t idx1 = ((size_t)(b * MM + mr + 8) * HH) + col;
            float a0 = o[nj][0] * inv0, a1 = o[nj][1] * inv0;
            float a2 = o[nj][2] * inv1, a3 = o[nj][3] * inv1;
            *(uint32_t*)(aoh + idx0) = packbf(a0, a1);
            *(uint32_t*)(aoh + idx1) = packbf(a2, a3);
            *(uint32_t*)(aol + idx0) = packbf_lo(a0, a1);
            *(uint32_t*)(aol + idx1) = packbf_lo(a2, a3);
        }
    }
}

// ---------------------------------------------------------------------------
extern "C" void kernel_launch(void* const* d_in, const int* in_sizes, int n_in,
                              void* d_out, int out_size) {
    const float* query  = (const float*)d_in[0];
    const float* key    = (const float*)d_in[1];
    const float* value  = (const float*)d_in[2];
    const float* key_pe = (const float*)d_in[3];
    const float* Wq     = (const float*)d_in[4];
    const float* Wk     = (const float*)d_in[5];
    const float* Wv     = (const float*)d_in[6];
    const float* Wo     = (const float*)d_in[7];
    float* out = (float*)d_out;

    __nv_bfloat16 *iqh, *iql, *ikh, *ikl, *ivh, *ivl;
    __nv_bfloat16 *hqh, *hql, *hkh, *hkl, *hvh, *hvl;
    __nv_bfloat16 *aoh, *aol, *wh, *wl, *peh, *pel;
    float* spb;
    cudaGetSymbolAddress((void**)&iqh, g_iqh); cudaGetSymbolAddress((void**)&iql, g_iql);
    cudaGetSymbolAddress((void**)&ikh, g_ikh); cudaGetSymbolAddress((void**)&ikl, g_ikl);
    cudaGetSymbolAddress((void**)&ivh, g_ivh); cudaGetSymbolAddress((void**)&ivl, g_ivl);
    cudaGetSymbolAddress((void**)&hqh, g_hqh); cudaGetSymbolAddress((void**)&hql, g_hql);
    cudaGetSymbolAddress((void**)&hkh, g_hkh); cudaGetSymbolAddress((void**)&hkl, g_hkl);
    cudaGetSymbolAddress((void**)&hvh, g_hvh); cudaGetSymbolAddress((void**)&hvl, g_hvl);
    cudaGetSymbolAddress((void**)&aoh, g_aoh); cudaGetSymbolAddress((void**)&aol, g_aol);
    cudaGetSymbolAddress((void**)&wh, g_wh);   cudaGetSymbolAddress((void**)&wl, g_wl);
    cudaGetSymbolAddress((void**)&peh, g_peh); cudaGetSymbolAddress((void**)&pel, g_pel);
    cudaGetSymbolAddress((void**)&spb, g_sp);

    static bool attr_set = false;
    if (!attr_set) {
        cudaFuncSetAttribute(attn3, cudaFuncAttributeMaxDynamicSharedMemorySize,
                             ATTN_SMEM);
        attr_set = true;
    }

    // splits
    split_bf16<<<BB * MM * HH / 4 / 256, 256>>>(query, iqh, iql, BB * MM * HH / 4);
    split_bf16<<<BB * NN * HH / 4 / 256, 256>>>(key, ikh, ikl, BB * NN * HH / 4);
    split_bf16<<<BB * NN * HH / 4 / 256, 256>>>(value, ivh, ivl, BB * NN * HH / 4);
    split_w4<<<dim3(HH * HH / 4 / 256, 4), 256>>>(Wq, Wk, Wv, Wo, wh, wl);
    split_pe<<<DD * LL / 256, 256>>>(key_pe, peh, pel);

    // projections -> head-layout bf16 hi/lo (q scaled by 1/8)
    gemm_mma<1><<<dim3(BB * MM / 128, 4), 256>>>(iqh, iql, wh, wl,
                                                 nullptr, hqh, hql, MM);
    gemm_mma<2><<<dim3(BB * NN / 128, 4), 256>>>(ikh, ikl, wh + (size_t)HH * HH,
                                                 wl + (size_t)HH * HH,
                                                 nullptr, hkh, hkl, NN);
    gemm_mma<2><<<dim3(BB * NN / 128, 4), 256>>>(ivh, ivl, wh + 2 * (size_t)HH * HH,
                                                 wl + 2 * (size_t)HH * HH,
                                                 nullptr, hvh, hvl, NN);

    // positional score table
    gemm_sp<<<dim3(MM / 128, LL / 128, 64), 256>>>(hqh, hql, peh, pel, spb);

    // flash banded attention
    attn3<<<dim3(MM / 64, 64), 128, ATTN_SMEM>>>(hqh, hql, hkh, hkl, hvh, hvl,
                                                 spb, aoh, aol);

    // output projection (fp32 out)
    gemm_mma<0><<<dim3(BB * MM / 128, 4), 256>>>(aoh, aol, wh + 3 * (size_t)HH * HH,
                                                 wl + 3 * (size_t)HH * HH,
                                                 out, nullptr, nullptr, MM);
}